// round 12
// baseline (speedup 1.0000x reference)
#include <cuda_runtime.h>
#include <cstdint>

#define T_TOK 8192
#define D_DIM 1024
#define E_EXP 8
#define F_DIM 2048
#define NSLOT (2 * T_TOK)

// ---------------- device-global scratch ----------------
__device__ int   g_cnt[E_EXP];
__device__ int   g_list[E_EXP * T_TOK];
__device__ float g_probs[NSLOT];
__device__ float g_xr[(size_t)T_TOK * D_DIM];  // tf32-rounded x
__device__ float g_Hs[(size_t)NSLOT * F_DIM];  // silu(x@w1), exact fp32
__device__ float g_H[(size_t)NSLOT * F_DIM];   // tf32-rounded silu*C3
__device__ float g_Y[(size_t)NSLOT * D_DIM];

// ---------------- helpers ----------------
__device__ __forceinline__ uint32_t smem_u32(const void* p) {
    uint32_t a;
    asm("{ .reg .u64 t; cvta.to.shared.u64 t, %1; cvt.u32.u64 %0, t; }" : "=r"(a) : "l"(p));
    return a;
}
__device__ __forceinline__ float to_tf32(float x) {
    uint32_t r;
    asm("cvt.rna.tf32.f32 %0, %1;" : "=r"(r) : "f"(x));
    return __uint_as_float(r);
}
__device__ __forceinline__ uint32_t lds_tf32(const float* p) {
    uint32_t r;
    asm("cvt.rna.tf32.f32 %0, %1;" : "=r"(r) : "f"(*p));
    return r;
}
#define CP16(dst, src) asm volatile("cp.async.cg.shared.global [%0], [%1], 16;" :: "r"(dst), "l"(src))

// mbarrier pipeline primitives (.noinc is load-bearing — R10 lesson)
#define MBAR_INIT(mb, c)  asm volatile("mbarrier.init.shared.b64 [%0], %1;" :: "r"(mb), "r"((uint32_t)(c)) : "memory")
#define MBAR_ARRIVE(mb)   asm volatile("mbarrier.arrive.shared.b64 _, [%0];" :: "r"(mb) : "memory")
#define CPMBAR_ARRIVE(mb) asm volatile("cp.async.mbarrier.arrive.noinc.shared.b64 [%0];" :: "r"(mb) : "memory")
__device__ __forceinline__ void mbar_wait(uint32_t mb, uint32_t parity) {
    uint32_t done;
    do {
        asm volatile("{ .reg .pred p; mbarrier.try_wait.parity.shared.b64 p, [%1], %2; selp.b32 %0, 1, 0, p; }"
                     : "=r"(done) : "r"(mb), "r"(parity) : "memory");
    } while (!done);
}

#define MMA_TF32(c, a, b)                                                          \
    asm volatile("mma.sync.aligned.m16n8k8.row.col.f32.tf32.tf32.f32 "             \
                 "{%0,%1,%2,%3}, {%4,%5,%6,%7}, {%8,%9}, {%0,%1,%2,%3};"           \
                 : "+f"((c)[0]), "+f"((c)[1]), "+f"((c)[2]), "+f"((c)[3])          \
                 : "r"((a)[0]), "r"((a)[1]), "r"((a)[2]), "r"((a)[3]),             \
                   "r"((b)[0]), "r"((b)[1]))

// smem strides (floats): A rows padded to 36 (144B), B rows padded to 136 (544B)
#define AST 36
#define BST 136
#define A_BYTES (128 * AST * 4)   // 18432
#define B_BYTES (32 * BST * 4)    // 17408
// smem map: [0..512) slots, [512..560) mbarriers, tiles @1024
#define MBF(sb, s) ((sb) + 512 + (s) * 8)
#define MBE(sb, s) ((sb) + 536 + (s) * 8)

#define NT 128   // threads per CTA

// ---------------- init ----------------
__global__ void init_kernel() {
    if (threadIdx.x < E_EXP) g_cnt[threadIdx.x] = 0;
}

// ---------------- pre-round x to tf32 ----------------
__global__ void __launch_bounds__(256) round_x_kernel(const float4* __restrict__ x,
                                                      float4* __restrict__ xr) {
    int i = blockIdx.x * 256 + threadIdx.x;
    const int n4 = T_TOK * D_DIM / 4;
    int stride = gridDim.x * 256;
    for (; i < n4; i += stride) {
        float4 v = x[i];
        v.x = to_tf32(v.x); v.y = to_tf32(v.y);
        v.z = to_tf32(v.z); v.w = to_tf32(v.w);
        xr[i] = v;
    }
}

// ---------------- gating (proven) ----------------
__global__ void __launch_bounds__(256) gate_kernel(const float* __restrict__ x,
                                                   const float* __restrict__ wg) {
    __shared__ float swg[E_EXP][D_DIM];
    int tid = threadIdx.x;
    for (int i = tid; i < D_DIM * E_EXP; i += 256) {
        int d = i >> 3, e = i & 7;
        swg[e][d] = wg[i];
    }
    __syncthreads();

    int warp = tid >> 5, lane = tid & 31;
    int t = blockIdx.x * 8 + warp;
    const float* xr = x + (size_t)t * D_DIM;

    float acc[E_EXP];
#pragma unroll
    for (int e = 0; e < E_EXP; e++) acc[e] = 0.f;
    for (int d = lane; d < D_DIM; d += 32) {
        float xv = xr[d];
#pragma unroll
        for (int e = 0; e < E_EXP; e++) acc[e] = fmaf(xv, swg[e][d], acc[e]);
    }
#pragma unroll
    for (int e = 0; e < E_EXP; e++)
#pragma unroll
        for (int o = 16; o > 0; o >>= 1)
            acc[e] += __shfl_xor_sync(0xffffffffu, acc[e], o);

    if (lane == 0) {
        int e0 = 0; float l0 = acc[0];
#pragma unroll
        for (int e = 1; e < E_EXP; e++) if (acc[e] > l0) { l0 = acc[e]; e0 = e; }
        int e1 = -1; float l1 = -3.0e38f;
#pragma unroll
        for (int e = 0; e < E_EXP; e++) {
            if (e == e0) continue;
            if (acc[e] > l1) { l1 = acc[e]; e1 = e; }
        }
        float ex  = __expf(l1 - l0);
        float inv = 1.f / (1.f + ex);
        g_probs[2 * t]     = inv;
        g_probs[2 * t + 1] = ex * inv;
        int p0 = atomicAdd(&g_cnt[e0], 1);
        g_list[e0 * T_TOK + p0] = 2 * t;
        int p1 = atomicAdd(&g_cnt[e1], 1);
        g_list[e1 * T_TOK + p1] = 2 * t + 1;
    }
}

// =============================================================================
// GEMM core: 128x128 CTA tile, 128 threads, 4 warps (2m x 2n), warp tile 64x64.
// 3-stage cp.async + mbarrier pipeline. EPI: 0 = raw store, 1 = silu store,
// 2 = mul-by-gHs + tf32 round.
// =============================================================================
template <int EPI>
__device__ __forceinline__ void gemm_core(const float* __restrict__ Asrc,  // gathered rows base
                                          int a_is_slot_pair,              // 1: slot>>1 row (xr), 0: slot row (g_H)
                                          int a_ld,                        // leading dim of Asrc rows
                                          const float* __restrict__ W,     // weight block, ld = w_ld
                                          int w_ld,
                                          int NCH,
                                          float* __restrict__ Dst, int d_ld, int dcol0,
                                          int n_e, int m0, char* smem) {
    int* slots = (int*)smem;
    uint32_t sb = smem_u32(smem);
    int tid = threadIdx.x, wid = tid >> 5, lane = tid & 31;

    if (tid == 0) {
#pragma unroll
        for (int s = 0; s < 3; s++) { MBAR_INIT(MBF(sb, s), NT); MBAR_INIT(MBE(sb, s), NT); }
    }
    __syncthreads();

    auto issue = [&](int ci, int s) {
        int k0 = ci * 32;
        uint32_t base = sb + 1024 + s * (A_BYTES + B_BYTES);
#pragma unroll
        for (int it = 0; it < 8; it++) {                 // A: 128 rows x 8 quads
            int idx = it * NT + tid;
            int row = idx >> 3, kq = idx & 7;
            int r = a_is_slot_pair ? (slots[row] >> 1) : slots[row];
            const float* src = Asrc + (size_t)r * a_ld + k0 + kq * 4;
            CP16(base + row * 144 + kq * 16, src);
        }
        uint32_t bb = base + A_BYTES;
#pragma unroll
        for (int it = 0; it < 8; it++) {                 // B: 32 k-rows x 32 quads
            int idx = it * NT + tid;
            int kr = idx >> 5, nq = idx & 31;
            CP16(bb + kr * 544 + nq * 16, W + (size_t)(k0 + kr) * w_ld + nq * 4);
        }
    };

    issue(0, 0); CPMBAR_ARRIVE(MBF(sb, 0));
    issue(1, 1); CPMBAR_ARRIVE(MBF(sb, 1));

    int g = lane >> 2, t = lane & 3;
    int m0w = (wid & 1) * 64, n0w = (wid >> 1) * 64;

    float c[4][8][4];
#pragma unroll
    for (int a = 0; a < 4; a++)
#pragma unroll
        for (int b = 0; b < 8; b++)
#pragma unroll
            for (int r = 0; r < 4; r++) c[a][b][r] = 0.f;

    int cs = 0, ck = 0;
    int ps = 2, pk = 0;
    for (int ci = 0; ci < NCH; ci++) {
        if (ci + 2 < NCH) {
            if (pk) mbar_wait(MBE(sb, ps), (pk - 1) & 1);
            issue(ci + 2, ps);
            CPMBAR_ARRIVE(MBF(sb, ps));
            if (++ps == 3) { ps = 0; ++pk; }
        }
        mbar_wait(MBF(sb, cs), ck);

        const float* As = (const float*)(smem + 1024 + cs * (A_BYTES + B_BYTES));
        const float* Bs = As + A_BYTES / 4;

#pragma unroll
        for (int kk = 0; kk < 4; kk++) {
            uint32_t af[4][4], bf[8][2];
#pragma unroll
            for (int mf = 0; mf < 4; mf++) {
                const float* ap = As + (m0w + mf * 16 + g) * AST + kk * 8 + t;
                af[mf][0] = __float_as_uint(ap[0]);
                af[mf][1] = __float_as_uint(ap[8 * AST]);
                af[mf][2] = __float_as_uint(ap[4]);
                af[mf][3] = __float_as_uint(ap[8 * AST + 4]);
            }
#pragma unroll
            for (int nf = 0; nf < 8; nf++) {
                const float* bp = Bs + (kk * 8 + t) * BST + n0w + nf * 8 + g;
                bf[nf][0] = lds_tf32(bp);
                bf[nf][1] = lds_tf32(bp + 4 * BST);
            }
#pragma unroll
            for (int mf = 0; mf < 4; mf++)
#pragma unroll
                for (int nf = 0; nf < 8; nf++)
                    MMA_TF32(c[mf][nf], af[mf], bf[nf]);
        }
        MBAR_ARRIVE(MBE(sb, cs));
        if (++cs == 3) { cs = 0; ck ^= 1; }
    }

    // ---- epilogue ----
#pragma unroll
    for (int mf = 0; mf < 4; mf++) {
#pragma unroll
        for (int half = 0; half < 2; half++) {
            int row = m0w + mf * 16 + g + 8 * half;
            if (m0 + row >= n_e) continue;
            int slot = slots[row];
            float* dp = Dst + (size_t)slot * d_ld + dcol0;
            const float* sp = (EPI == 2) ? (g_Hs + (size_t)slot * (size_t)F_DIM + dcol0) : nullptr;
#pragma unroll
            for (int nf = 0; nf < 8; nf++) {
                int col = n0w + nf * 8 + 2 * t;
                float v0 = c[mf][nf][2 * half + 0];
                float v1 = c[mf][nf][2 * half + 1];
                float2 o;
                if (EPI == 0) {
                    o.x = v0; o.y = v1;
                } else if (EPI == 1) {
                    o.x = v0 / (1.f + __expf(-v0));
                    o.y = v1 / (1.f + __expf(-v1));
                } else {
                    float2 s = *(const float2*)(sp + col);
                    o.x = to_tf32(s.x * v0);
                    o.y = to_tf32(s.y * v1);
                }
                *(float2*)(dp + col) = o;
            }
        }
    }
}

// ============= GEMM1a: g_Hs = silu(gather(xr) @ w1) ===========================
__global__ void __launch_bounds__(NT, 2) gemm1a_kernel(const float* __restrict__ xr,
                                                       const float* __restrict__ w1) {
    int e   = blockIdx.z;
    int n_e = g_cnt[e];
    int m0  = blockIdx.x * 128;
    if (m0 >= n_e) return;
    int f0  = blockIdx.y * 128;

    extern __shared__ char smem[];
    int* slots = (int*)smem;
    int tid = threadIdx.x;
    if (tid < 128) {
        int m = m0 + tid;
        slots[tid] = g_list[e * T_TOK + (m < n_e ? m : m0)];
    }
    gemm_core<1>(xr, 1, D_DIM, w1 + (size_t)e * D_DIM * F_DIM + f0, F_DIM,
                 D_DIM / 32, g_Hs, F_DIM, f0, n_e, m0, smem);
}

// ============= GEMM1b: g_H = tf32(g_Hs * (gather(xr) @ w3)) ===================
__global__ void __launch_bounds__(NT, 2) gemm1b_kernel(const float* __restrict__ xr,
                                                       const float* __restrict__ w3) {
    int e   = blockIdx.z;
    int n_e = g_cnt[e];
    int m0  = blockIdx.x * 128;
    if (m0 >= n_e) return;
    int f0  = blockIdx.y * 128;

    extern __shared__ char smem[];
    int* slots = (int*)smem;
    int tid = threadIdx.x;
    if (tid < 128) {
        int m = m0 + tid;
        slots[tid] = g_list[e * T_TOK + (m < n_e ? m : m0)];
    }
    gemm_core<2>(xr, 1, D_DIM, w3 + (size_t)e * D_DIM * F_DIM + f0, F_DIM,
                 D_DIM / 32, g_H, F_DIM, f0, n_e, m0, smem);
}

// ============= GEMM2: Y = gather(g_H) @ w2 ====================================
__global__ void __launch_bounds__(NT, 2) gemm2_kernel(const float* __restrict__ w2) {
    int e   = blockIdx.z;
    int n_e = g_cnt[e];
    int m0  = blockIdx.x * 128;
    if (m0 >= n_e) return;
    int n0  = blockIdx.y * 128;

    extern __shared__ char smem[];
    int* slots = (int*)smem;
    int tid = threadIdx.x;
    if (tid < 128) {
        int m = m0 + tid;
        slots[tid] = g_list[e * T_TOK + (m < n_e ? m : m0)];
    }
    gemm_core<0>(g_H, 0, F_DIM, w2 + (size_t)e * F_DIM * D_DIM + n0, D_DIM,
                 F_DIM / 32, g_Y, D_DIM, n0, n_e, m0, smem);
}

// ---------------- combine ----------------
__global__ void __launch_bounds__(256) combine_kernel(float* __restrict__ out) {
    int idx = blockIdx.x * 256 + threadIdx.x;
    int t   = idx / (D_DIM / 4);
    int d4  = idx % (D_DIM / 4);
    float p0 = g_probs[2 * t], p1 = g_probs[2 * t + 1];
    const float4* y0 = (const float4*)(g_Y + (size_t)(2 * t) * D_DIM) + d4;
    const float4* y1 = (const float4*)(g_Y + (size_t)(2 * t + 1) * D_DIM) + d4;
    float4 a = *y0, b = *y1, o;
    o.x = p0 * a.x + p1 * b.x;
    o.y = p0 * a.y + p1 * b.y;
    o.z = p0 * a.z + p1 * b.z;
    o.w = p0 * a.w + p1 * b.w;
    *((float4*)(out + (size_t)t * D_DIM) + d4) = o;
}

// ---------------- launch ----------------
extern "C" void kernel_launch(void* const* d_in, const int* in_sizes, int n_in,
                              void* d_out, int out_size) {
    const float* x  = (const float*)d_in[0];
    const float* wg = (const float*)d_in[1];
    const float* w1 = (const float*)d_in[2];
    const float* w3 = (const float*)d_in[3];
    const float* w2 = (const float*)d_in[4];
    float* out = (float*)d_out;

    const int SMEM_G = 1024 + 3 * (A_BYTES + B_BYTES);  // 108544
    cudaFuncSetAttribute(gemm1a_kernel, cudaFuncAttributeMaxDynamicSharedMemorySize, SMEM_G);
    cudaFuncSetAttribute(gemm1b_kernel, cudaFuncAttributeMaxDynamicSharedMemorySize, SMEM_G);
    cudaFuncSetAttribute(gemm2_kernel,  cudaFuncAttributeMaxDynamicSharedMemorySize, SMEM_G);

    float* xr;
    cudaGetSymbolAddress((void**)&xr, g_xr);

    init_kernel<<<1, 32>>>();
    round_x_kernel<<<2048, 256>>>((const float4*)x, (float4*)xr);
    gate_kernel<<<T_TOK / 8, 256>>>(x, wg);
    gemm1a_kernel<<<dim3(T_TOK / 128, F_DIM / 128, E_EXP), NT, SMEM_G>>>(xr, w1);
    gemm1b_kernel<<<dim3(T_TOK / 128, F_DIM / 128, E_EXP), NT, SMEM_G>>>(xr, w3);
    gemm2_kernel<<<dim3(T_TOK / 128, D_DIM / 128, E_EXP), NT, SMEM_G>>>(w2);
    combine_kernel<<<(T_TOK * D_DIM / 4) / 256, 256>>>(out);
}

// round 13
// speedup vs baseline: 1.0785x; 1.0785x over previous
#include <cuda_runtime.h>
#include <cstdint>

#define T_TOK 8192
#define D_DIM 1024
#define E_EXP 8
#define F_DIM 2048
#define NSLOT (2 * T_TOK)

// ---------------- device-global scratch ----------------
__device__ int   g_cnt[E_EXP];
__device__ int   g_list[E_EXP * T_TOK];
__device__ float g_probs[NSLOT];
__device__ float g_xr[(size_t)T_TOK * D_DIM];  // tf32-rounded x
__device__ float g_Hs[(size_t)NSLOT * F_DIM];  // silu(x@w1), exact fp32
__device__ float g_H[(size_t)NSLOT * F_DIM];   // tf32-rounded silu*C3
__device__ float g_Y[(size_t)NSLOT * D_DIM];

// ---------------- helpers ----------------
__device__ __forceinline__ uint32_t smem_u32(const void* p) {
    uint32_t a;
    asm("{ .reg .u64 t; cvta.to.shared.u64 t, %1; cvt.u32.u64 %0, t; }" : "=r"(a) : "l"(p));
    return a;
}
__device__ __forceinline__ float to_tf32(float x) {
    uint32_t r;
    asm("cvt.rna.tf32.f32 %0, %1;" : "=r"(r) : "f"(x));
    return __uint_as_float(r);
}
__device__ __forceinline__ uint32_t lds_tf32(const float* p) {
    uint32_t r;
    asm("cvt.rna.tf32.f32 %0, %1;" : "=r"(r) : "f"(*p));
    return r;
}
#define CP16(dst, src) asm volatile("cp.async.cg.shared.global [%0], [%1], 16;" :: "r"(dst), "l"(src))

// mbarrier pipeline primitives (.noinc is load-bearing — R10 lesson)
#define MBAR_INIT(mb, c)  asm volatile("mbarrier.init.shared.b64 [%0], %1;" :: "r"(mb), "r"((uint32_t)(c)) : "memory")
#define MBAR_ARRIVE(mb)   asm volatile("mbarrier.arrive.shared.b64 _, [%0];" :: "r"(mb) : "memory")
#define CPMBAR_ARRIVE(mb) asm volatile("cp.async.mbarrier.arrive.noinc.shared.b64 [%0];" :: "r"(mb) : "memory")
__device__ __forceinline__ void mbar_wait(uint32_t mb, uint32_t parity) {
    uint32_t done;
    do {
        asm volatile("{ .reg .pred p; mbarrier.try_wait.parity.shared.b64 p, [%1], %2; selp.b32 %0, 1, 0, p; }"
                     : "=r"(done) : "r"(mb), "r"(parity) : "memory");
    } while (!done);
}

#define MMA_TF32(c, a, b)                                                          \
    asm volatile("mma.sync.aligned.m16n8k8.row.col.f32.tf32.tf32.f32 "             \
                 "{%0,%1,%2,%3}, {%4,%5,%6,%7}, {%8,%9}, {%0,%1,%2,%3};"           \
                 : "+f"((c)[0]), "+f"((c)[1]), "+f"((c)[2]), "+f"((c)[3])          \
                 : "r"((a)[0]), "r"((a)[1]), "r"((a)[2]), "r"((a)[3]),             \
                   "r"((b)[0]), "r"((b)[1]))

// smem strides (floats): A rows padded to 36 (144B), B rows padded to 136 (544B)
#define AST 36
#define BST 136
#define A_BYTES (128 * AST * 4)   // 18432
#define B_BYTES (32 * BST * 4)    // 17408
// smem map: [0..512) slots, [512..560) mbarriers (3 full @512+8s, 3 empty @536+8s), tiles @1024
#define MBF(sb, s) ((sb) + 512 + (s) * 8)
#define MBE(sb, s) ((sb) + 536 + (s) * 8)

// ---------------- init ----------------
__global__ void init_kernel() {
    if (threadIdx.x < E_EXP) g_cnt[threadIdx.x] = 0;
}

// ---------------- pre-round x to tf32 (32 MB only) ----------------
__global__ void __launch_bounds__(256) round_x_kernel(const float4* __restrict__ x,
                                                      float4* __restrict__ xr) {
    int i = blockIdx.x * 256 + threadIdx.x;
    const int n4 = T_TOK * D_DIM / 4;
    int stride = gridDim.x * 256;
    for (; i < n4; i += stride) {
        float4 v = x[i];
        v.x = to_tf32(v.x); v.y = to_tf32(v.y);
        v.z = to_tf32(v.z); v.w = to_tf32(v.w);
        xr[i] = v;
    }
}

// ---------------- gating (proven) ----------------
__global__ void __launch_bounds__(256) gate_kernel(const float* __restrict__ x,
                                                   const float* __restrict__ wg) {
    __shared__ float swg[E_EXP][D_DIM];
    int tid = threadIdx.x;
    for (int i = tid; i < D_DIM * E_EXP; i += 256) {
        int d = i >> 3, e = i & 7;
        swg[e][d] = wg[i];
    }
    __syncthreads();

    int warp = tid >> 5, lane = tid & 31;
    int t = blockIdx.x * 8 + warp;
    const float* xr = x + (size_t)t * D_DIM;

    float acc[E_EXP];
#pragma unroll
    for (int e = 0; e < E_EXP; e++) acc[e] = 0.f;
    for (int d = lane; d < D_DIM; d += 32) {
        float xv = xr[d];
#pragma unroll
        for (int e = 0; e < E_EXP; e++) acc[e] = fmaf(xv, swg[e][d], acc[e]);
    }
#pragma unroll
    for (int e = 0; e < E_EXP; e++)
#pragma unroll
        for (int o = 16; o > 0; o >>= 1)
            acc[e] += __shfl_xor_sync(0xffffffffu, acc[e], o);

    if (lane == 0) {
        int e0 = 0; float l0 = acc[0];
#pragma unroll
        for (int e = 1; e < E_EXP; e++) if (acc[e] > l0) { l0 = acc[e]; e0 = e; }
        int e1 = -1; float l1 = -3.0e38f;
#pragma unroll
        for (int e = 0; e < E_EXP; e++) {
            if (e == e0) continue;
            if (acc[e] > l1) { l1 = acc[e]; e1 = e; }
        }
        float ex  = __expf(l1 - l0);
        float inv = 1.f / (1.f + ex);
        g_probs[2 * t]     = inv;
        g_probs[2 * t + 1] = ex * inv;
        int p0 = atomicAdd(&g_cnt[e0], 1);
        g_list[e0 * T_TOK + p0] = 2 * t;
        int p1 = atomicAdd(&g_cnt[e1], 1);
        g_list[e1 * T_TOK + p1] = 2 * t + 1;
    }
}

// ============= GEMM1a: g_Hs = silu(gather(xr) @ w1), mbarrier pipeline ========
__global__ void __launch_bounds__(256, 2) gemm1a_kernel(const float* __restrict__ xr,
                                                        const float* __restrict__ w1) {
    int e   = blockIdx.z;
    int n_e = g_cnt[e];
    int m0  = blockIdx.x * 128;
    if (m0 >= n_e) return;
    int f0  = blockIdx.y * 128;

    extern __shared__ char smem[];
    int* slots = (int*)smem;
    uint32_t sb = smem_u32(smem);
    int tid = threadIdx.x, wid = tid >> 5, lane = tid & 31;

    if (tid < 128) {
        int m = m0 + tid;
        slots[tid] = g_list[e * T_TOK + (m < n_e ? m : m0)];
    }
    if (tid == 0) {
#pragma unroll
        for (int s = 0; s < 3; s++) { MBAR_INIT(MBF(sb, s), 256); MBAR_INIT(MBE(sb, s), 256); }
    }
    __syncthreads();

    const float* W = w1 + (size_t)e * D_DIM * F_DIM + f0;

    auto issue = [&](int ci, int s) {
        int k0 = ci * 32;
        uint32_t base = sb + 1024 + s * (A_BYTES + B_BYTES);
#pragma unroll
        for (int it = 0; it < 4; it++) {
            int idx = it * 256 + tid;
            int row = idx >> 3, kq = idx & 7;
            const float* src = xr + (size_t)(slots[row] >> 1) * D_DIM + k0 + kq * 4;
            CP16(base + row * 144 + kq * 16, src);
        }
        uint32_t bb = base + A_BYTES;
#pragma unroll
        for (int it = 0; it < 4; it++) {
            int idx = it * 256 + tid;
            int kr = idx >> 5, nq = idx & 31;
            CP16(bb + kr * 544 + nq * 16, W + (size_t)(k0 + kr) * F_DIM + nq * 4);
        }
    };

    issue(0, 0); CPMBAR_ARRIVE(MBF(sb, 0));
    issue(1, 1); CPMBAR_ARRIVE(MBF(sb, 1));

    // ---- phase skew: break warp lockstep (one-time, data-path neutral) ----
    __nanosleep(wid * 32);

    int g = lane >> 2, t = lane & 3;
    int m0w = (wid & 1) * 64, n0w = (wid >> 1) * 32;

    float c[4][4][4];
#pragma unroll
    for (int a = 0; a < 4; a++)
#pragma unroll
        for (int b = 0; b < 4; b++)
#pragma unroll
            for (int r = 0; r < 4; r++) c[a][b][r] = 0.f;

    const int NCH = D_DIM / 32;  // 32
    int cs = 0, ck = 0;          // consumer stage, parity
    int ps = 2, pk = 0;          // producer stage, reuse count
    for (int ci = 0; ci < NCH; ci++) {
        if (ci + 2 < NCH) {
            if (pk) mbar_wait(MBE(sb, ps), (pk - 1) & 1);
            issue(ci + 2, ps);
            CPMBAR_ARRIVE(MBF(sb, ps));
            if (++ps == 3) { ps = 0; ++pk; }
        }
        mbar_wait(MBF(sb, cs), ck);

        const float* As = (const float*)(smem + 1024 + cs * (A_BYTES + B_BYTES));
        const float* Bs = As + A_BYTES / 4;

#pragma unroll
        for (int kk = 0; kk < 4; kk++) {
            uint32_t af[4][4], bf[4][2];
#pragma unroll
            for (int mf = 0; mf < 4; mf++) {
                const float* ap = As + (m0w + mf * 16 + g) * AST + kk * 8 + t;
                af[mf][0] = __float_as_uint(ap[0]);
                af[mf][1] = __float_as_uint(ap[8 * AST]);
                af[mf][2] = __float_as_uint(ap[4]);
                af[mf][3] = __float_as_uint(ap[8 * AST + 4]);
            }
#pragma unroll
            for (int nf = 0; nf < 4; nf++) {
                const float* bp = Bs + (kk * 8 + t) * BST + n0w + nf * 8 + g;
                bf[nf][0] = lds_tf32(bp);
                bf[nf][1] = lds_tf32(bp + 4 * BST);
            }
#pragma unroll
            for (int mf = 0; mf < 4; mf++)
#pragma unroll
                for (int nf = 0; nf < 4; nf++)
                    MMA_TF32(c[mf][nf], af[mf], bf[nf]);
        }
        MBAR_ARRIVE(MBE(sb, cs));
        if (++cs == 3) { cs = 0; ck ^= 1; }
    }

    // epilogue: store silu(c) exact fp32
#pragma unroll
    for (int mf = 0; mf < 4; mf++) {
#pragma unroll
        for (int half = 0; half < 2; half++) {
            int row = m0w + mf * 16 + g + 8 * half;
            if (m0 + row >= n_e) continue;
            float* hp = g_Hs + (size_t)slots[row] * F_DIM + f0;
#pragma unroll
            for (int nf = 0; nf < 4; nf++) {
                float v0 = c[mf][nf][2 * half + 0];
                float v1 = c[mf][nf][2 * half + 1];
                float2 o;
                o.x = v0 / (1.f + __expf(-v0));
                o.y = v1 / (1.f + __expf(-v1));
                *(float2*)(hp + n0w + nf * 8 + 2 * t) = o;
            }
        }
    }
}

// ============= GEMM1b: g_H = tf32(g_Hs * (gather(xr) @ w3)), mbarrier =========
__global__ void __launch_bounds__(256, 2) gemm1b_kernel(const float* __restrict__ xr,
                                                        const float* __restrict__ w3) {
    int e   = blockIdx.z;
    int n_e = g_cnt[e];
    int m0  = blockIdx.x * 128;
    if (m0 >= n_e) return;
    int f0  = blockIdx.y * 128;

    extern __shared__ char smem[];
    int* slots = (int*)smem;
    uint32_t sb = smem_u32(smem);
    int tid = threadIdx.x, wid = tid >> 5, lane = tid & 31;

    if (tid < 128) {
        int m = m0 + tid;
        slots[tid] = g_list[e * T_TOK + (m < n_e ? m : m0)];
    }
    if (tid == 0) {
#pragma unroll
        for (int s = 0; s < 3; s++) { MBAR_INIT(MBF(sb, s), 256); MBAR_INIT(MBE(sb, s), 256); }
    }
    __syncthreads();

    const float* W = w3 + (size_t)e * D_DIM * F_DIM + f0;

    auto issue = [&](int ci, int s) {
        int k0 = ci * 32;
        uint32_t base = sb + 1024 + s * (A_BYTES + B_BYTES);
#pragma unroll
        for (int it = 0; it < 4; it++) {
            int idx = it * 256 + tid;
            int row = idx >> 3, kq = idx & 7;
            const float* src = xr + (size_t)(slots[row] >> 1) * D_DIM + k0 + kq * 4;
            CP16(base + row * 144 + kq * 16, src);
        }
        uint32_t bb = base + A_BYTES;
#pragma unroll
        for (int it = 0; it < 4; it++) {
            int idx = it * 256 + tid;
            int kr = idx >> 5, nq = idx & 31;
            CP16(bb + kr * 544 + nq * 16, W + (size_t)(k0 + kr) * F_DIM + nq * 4);
        }
    };

    issue(0, 0); CPMBAR_ARRIVE(MBF(sb, 0));
    issue(1, 1); CPMBAR_ARRIVE(MBF(sb, 1));

    __nanosleep(wid * 32);

    int g = lane >> 2, t = lane & 3;
    int m0w = (wid & 1) * 64, n0w = (wid >> 1) * 32;

    float c[4][4][4];
#pragma unroll
    for (int a = 0; a < 4; a++)
#pragma unroll
        for (int b = 0; b < 4; b++)
#pragma unroll
            for (int r = 0; r < 4; r++) c[a][b][r] = 0.f;

    const int NCH = D_DIM / 32;  // 32
    int cs = 0, ck = 0;
    int ps = 2, pk = 0;
    for (int ci = 0; ci < NCH; ci++) {
        if (ci + 2 < NCH) {
            if (pk) mbar_wait(MBE(sb, ps), (pk - 1) & 1);
            issue(ci + 2, ps);
            CPMBAR_ARRIVE(MBF(sb, ps));
            if (++ps == 3) { ps = 0; ++pk; }
        }
        mbar_wait(MBF(sb, cs), ck);

        const float* As = (const float*)(smem + 1024 + cs * (A_BYTES + B_BYTES));
        const float* Bs = As + A_BYTES / 4;

#pragma unroll
        for (int kk = 0; kk < 4; kk++) {
            uint32_t af[4][4], bf[4][2];
#pragma unroll
            for (int mf = 0; mf < 4; mf++) {
                const float* ap = As + (m0w + mf * 16 + g) * AST + kk * 8 + t;
                af[mf][0] = __float_as_uint(ap[0]);
                af[mf][1] = __float_as_uint(ap[8 * AST]);
                af[mf][2] = __float_as_uint(ap[4]);
                af[mf][3] = __float_as_uint(ap[8 * AST + 4]);
            }
#pragma unroll
            for (int nf = 0; nf < 4; nf++) {
                const float* bp = Bs + (kk * 8 + t) * BST + n0w + nf * 8 + g;
                bf[nf][0] = lds_tf32(bp);
                bf[nf][1] = lds_tf32(bp + 4 * BST);
            }
#pragma unroll
            for (int mf = 0; mf < 4; mf++)
#pragma unroll
                for (int nf = 0; nf < 4; nf++)
                    MMA_TF32(c[mf][nf], af[mf], bf[nf]);
        }
        MBAR_ARRIVE(MBE(sb, cs));
        if (++cs == 3) { cs = 0; ck ^= 1; }
    }

    // epilogue: H = rna_tf32(silu_stored * c3)
#pragma unroll
    for (int mf = 0; mf < 4; mf++) {
#pragma unroll
        for (int half = 0; half < 2; half++) {
            int row = m0w + mf * 16 + g + 8 * half;
            if (m0 + row >= n_e) continue;
            const float* sp = g_Hs + (size_t)slots[row] * F_DIM + f0;
            float* hp = g_H + (size_t)slots[row] * F_DIM + f0;
#pragma unroll
            for (int nf = 0; nf < 4; nf++) {
                float2 s = *(const float2*)(sp + n0w + nf * 8 + 2 * t);
                float2 o;
                o.x = to_tf32(s.x * c[mf][nf][2 * half + 0]);
                o.y = to_tf32(s.y * c[mf][nf][2 * half + 1]);
                *(float2*)(hp + n0w + nf * 8 + 2 * t) = o;
            }
        }
    }
}

// ======================= GEMM2: Y = H @ w2, mbarrier pipeline =================
__global__ void __launch_bounds__(256, 2) gemm2_kernel(const float* __restrict__ w2) {
    int e   = blockIdx.z;
    int n_e = g_cnt[e];
    int m0  = blockIdx.x * 128;
    if (m0 >= n_e) return;
    int n0  = blockIdx.y * 128;

    extern __shared__ char smem[];
    int* slots = (int*)smem;
    uint32_t sb = smem_u32(smem);
    int tid = threadIdx.x, wid = tid >> 5, lane = tid & 31;

    if (tid < 128) {
        int m = m0 + tid;
        slots[tid] = g_list[e * T_TOK + (m < n_e ? m : m0)];
    }
    if (tid == 0) {
#pragma unroll
        for (int s = 0; s < 3; s++) { MBAR_INIT(MBF(sb, s), 256); MBAR_INIT(MBE(sb, s), 256); }
    }
    __syncthreads();

    const float* W2 = w2 + (size_t)e * F_DIM * D_DIM + n0;

    auto issue = [&](int ci, int s) {
        int k0 = ci * 32;
        uint32_t base = sb + 1024 + s * (A_BYTES + B_BYTES);
#pragma unroll
        for (int it = 0; it < 4; it++) {
            int idx = it * 256 + tid;
            int row = idx >> 3, kq = idx & 7;
            const float* src = g_H + (size_t)slots[row] * F_DIM + k0 + kq * 4;
            CP16(base + row * 144 + kq * 16, src);
        }
        uint32_t bb = base + A_BYTES;
#pragma unroll
        for (int it = 0; it < 4; it++) {
            int idx = it * 256 + tid;
            int kr = idx >> 5, nq = idx & 31;
            CP16(bb + kr * 544 + nq * 16, W2 + (size_t)(k0 + kr) * D_DIM + nq * 4);
        }
    };

    issue(0, 0); CPMBAR_ARRIVE(MBF(sb, 0));
    issue(1, 1); CPMBAR_ARRIVE(MBF(sb, 1));

    __nanosleep(wid * 32);

    int g = lane >> 2, t = lane & 3;
    int m0w = (wid & 1) * 64, n0w = (wid >> 1) * 32;

    float c[4][4][4];
#pragma unroll
    for (int a = 0; a < 4; a++)
#pragma unroll
        for (int b = 0; b < 4; b++)
#pragma unroll
            for (int r = 0; r < 4; r++) c[a][b][r] = 0.f;

    const int NCH = F_DIM / 32;  // 64
    int cs = 0, ck = 0;
    int ps = 2, pk = 0;
    for (int ci = 0; ci < NCH; ci++) {
        if (ci + 2 < NCH) {
            if (pk) mbar_wait(MBE(sb, ps), (pk - 1) & 1);
            issue(ci + 2, ps);
            CPMBAR_ARRIVE(MBF(sb, ps));
            if (++ps == 3) { ps = 0; ++pk; }
        }
        mbar_wait(MBF(sb, cs), ck);

        const float* As = (const float*)(smem + 1024 + cs * (A_BYTES + B_BYTES));
        const float* Bs = As + A_BYTES / 4;

#pragma unroll
        for (int kk = 0; kk < 4; kk++) {
            uint32_t af[4][4], bf[4][2];
#pragma unroll
            for (int mf = 0; mf < 4; mf++) {
                const float* ap = As + (m0w + mf * 16 + g) * AST + kk * 8 + t;
                af[mf][0] = __float_as_uint(ap[0]);
                af[mf][1] = __float_as_uint(ap[8 * AST]);
                af[mf][2] = __float_as_uint(ap[4]);
                af[mf][3] = __float_as_uint(ap[8 * AST + 4]);
            }
#pragma unroll
            for (int nf = 0; nf < 4; nf++) {
                const float* bp = Bs + (kk * 8 + t) * BST + n0w + nf * 8 + g;
                bf[nf][0] = lds_tf32(bp);
                bf[nf][1] = lds_tf32(bp + 4 * BST);
            }
#pragma unroll
            for (int mf = 0; mf < 4; mf++)
#pragma unroll
                for (int nf = 0; nf < 4; nf++)
                    MMA_TF32(c[mf][nf], af[mf], bf[nf]);
        }
        MBAR_ARRIVE(MBE(sb, cs));
        if (++cs == 3) { cs = 0; ck ^= 1; }
    }

#pragma unroll
    for (int mf = 0; mf < 4; mf++) {
#pragma unroll
        for (int half = 0; half < 2; half++) {
            int row = m0w + mf * 16 + g + 8 * half;
            if (m0 + row >= n_e) continue;
            float* yp = g_Y + (size_t)slots[row] * D_DIM + n0;
#pragma unroll
            for (int nf = 0; nf < 4; nf++) {
                float2 o;
                o.x = c[mf][nf][2 * half + 0];
                o.y = c[mf][nf][2 * half + 1];
                *(float2*)(yp + n0w + nf * 8 + 2 * t) = o;
            }
        }
    }
}

// ---------------- combine ----------------
__global__ void __launch_bounds__(256) combine_kernel(float* __restrict__ out) {
    int idx = blockIdx.x * 256 + threadIdx.x;
    int t   = idx / (D_DIM / 4);
    int d4  = idx % (D_DIM / 4);
    float p0 = g_probs[2 * t], p1 = g_probs[2 * t + 1];
    const float4* y0 = (const float4*)(g_Y + (size_t)(2 * t) * D_DIM) + d4;
    const float4* y1 = (const float4*)(g_Y + (size_t)(2 * t + 1) * D_DIM) + d4;
    float4 a = *y0, b = *y1, o;
    o.x = p0 * a.x + p1 * b.x;
    o.y = p0 * a.y + p1 * b.y;
    o.z = p0 * a.z + p1 * b.z;
    o.w = p0 * a.w + p1 * b.w;
    *((float4*)(out + (size_t)t * D_DIM) + d4) = o;
}

// ---------------- launch ----------------
extern "C" void kernel_launch(void* const* d_in, const int* in_sizes, int n_in,
                              void* d_out, int out_size) {
    const float* x  = (const float*)d_in[0];
    const float* wg = (const float*)d_in[1];
    const float* w1 = (const float*)d_in[2];
    const float* w3 = (const float*)d_in[3];
    const float* w2 = (const float*)d_in[4];
    float* out = (float*)d_out;

    const int SMEM_G = 1024 + 3 * (A_BYTES + B_BYTES);  // 108544
    cudaFuncSetAttribute(gemm1a_kernel, cudaFuncAttributeMaxDynamicSharedMemorySize, SMEM_G);
    cudaFuncSetAttribute(gemm1b_kernel, cudaFuncAttributeMaxDynamicSharedMemorySize, SMEM_G);
    cudaFuncSetAttribute(gemm2_kernel,  cudaFuncAttributeMaxDynamicSharedMemorySize, SMEM_G);

    float* xr;
    cudaGetSymbolAddress((void**)&xr, g_xr);

    init_kernel<<<1, 32>>>();
    round_x_kernel<<<2048, 256>>>((const float4*)x, (float4*)xr);
    gate_kernel<<<T_TOK / 8, 256>>>(x, wg);
    gemm1a_kernel<<<dim3(T_TOK / 128, F_DIM / 128, E_EXP), 256, SMEM_G>>>(xr, w1);
    gemm1b_kernel<<<dim3(T_TOK / 128, F_DIM / 128, E_EXP), 256, SMEM_G>>>(xr, w3);
    gemm2_kernel<<<dim3(T_TOK / 128, D_DIM / 128, E_EXP), 256, SMEM_G>>>(w2);
    combine_kernel<<<(T_TOK * D_DIM / 4) / 256, 256>>>(out);
}

// round 14
// speedup vs baseline: 1.5936x; 1.4776x over previous
#include <cuda_runtime.h>
#include <cuda_fp16.h>
#include <cstdint>

#define T_TOK 8192
#define D_DIM 1024
#define E_EXP 8
#define F_DIM 2048
#define NSLOT (2 * T_TOK)

// ---------------- device-global scratch ----------------
__device__ int    g_cnt[E_EXP];
__device__ int    g_list[E_EXP * T_TOK];
__device__ float  g_probs[NSLOT];
__device__ __half g_xh[(size_t)T_TOK * D_DIM];          // fp16 x
__device__ __half g_w1t[(size_t)E_EXP * D_DIM * F_DIM]; // fp16, transposed [e][f][d]
__device__ __half g_w3t[(size_t)E_EXP * D_DIM * F_DIM]; // fp16, transposed [e][f][d]
__device__ __half g_w2t[(size_t)E_EXP * F_DIM * D_DIM]; // fp16, transposed [e][d][f]
__device__ float  g_Hs[(size_t)NSLOT * F_DIM];          // silu(x@w1), exact fp32
__device__ __half g_Hh[(size_t)NSLOT * F_DIM];          // fp16 H = fp16(silu * c3)
__device__ float  g_Y[(size_t)NSLOT * D_DIM];

// ---------------- helpers ----------------
__device__ __forceinline__ uint32_t smem_u32(const void* p) {
    uint32_t a;
    asm("{ .reg .u64 t; cvta.to.shared.u64 t, %1; cvt.u32.u64 %0, t; }" : "=r"(a) : "l"(p));
    return a;
}
#define CP16(dst, src) asm volatile("cp.async.cg.shared.global [%0], [%1], 16;" :: "r"(dst), "l"(src))

// mbarrier pipeline primitives (.noinc is load-bearing — R10 lesson)
#define MBAR_INIT(mb, c)  asm volatile("mbarrier.init.shared.b64 [%0], %1;" :: "r"(mb), "r"((uint32_t)(c)) : "memory")
#define MBAR_ARRIVE(mb)   asm volatile("mbarrier.arrive.shared.b64 _, [%0];" :: "r"(mb) : "memory")
#define CPMBAR_ARRIVE(mb) asm volatile("cp.async.mbarrier.arrive.noinc.shared.b64 [%0];" :: "r"(mb) : "memory")
__device__ __forceinline__ void mbar_wait(uint32_t mb, uint32_t parity) {
    uint32_t done;
    do {
        asm volatile("{ .reg .pred p; mbarrier.try_wait.parity.shared.b64 p, [%1], %2; selp.b32 %0, 1, 0, p; }"
                     : "=r"(done) : "r"(mb), "r"(parity) : "memory");
    } while (!done);
}

#define MMA_F16(c, a, b)                                                           \
    asm volatile("mma.sync.aligned.m16n8k16.row.col.f32.f16.f16.f32 "              \
                 "{%0,%1,%2,%3}, {%4,%5,%6,%7}, {%8,%9}, {%0,%1,%2,%3};"           \
                 : "+f"((c)[0]), "+f"((c)[1]), "+f"((c)[2]), "+f"((c)[3])          \
                 : "r"((a)[0]), "r"((a)[1]), "r"((a)[2]), "r"((a)[3]),             \
                   "r"((b)[0]), "r"((b)[1]))

// smem: tiles of 128 rows x 32 halves, rows padded to 40 halves (80 B).
// bank check: addr4 = 20g + t, 20g mod 32 = {0,20,8,28,16,4,24,12} — conflict-free.
#define ROW_H 40
#define TILE_BYTES (128 * ROW_H * 2)   // 10240
#define STG (2 * TILE_BYTES)           // 20480 (A + B)
// smem map: [0..512) slots, [512..560) mbarriers, tiles @1024
#define MBF(sb, s) ((sb) + 512 + (s) * 8)
#define MBE(sb, s) ((sb) + 536 + (s) * 8)

// ---------------- init ----------------
__global__ void init_kernel() {
    if (threadIdx.x < E_EXP) g_cnt[threadIdx.x] = 0;
}

// ---------------- convert x: fp32 -> fp16 ----------------
__global__ void __launch_bounds__(256) convert_x_kernel(const float4* __restrict__ x,
                                                        __half2* __restrict__ xh) {
    const int n4 = T_TOK * D_DIM / 4;
    int i = blockIdx.x * 256 + threadIdx.x;
    int stride = gridDim.x * 256;
    for (; i < n4; i += stride) {
        float4 v = x[i];
        xh[2 * i + 0] = __floats2half2_rn(v.x, v.y);
        xh[2 * i + 1] = __floats2half2_rn(v.z, v.w);
    }
}

// ------- transpose + convert: in fp32 [e][R][C] -> out fp16 [e][C][R] --------
__global__ void tconv_kernel(const float* __restrict__ in, __half* __restrict__ out,
                             int R, int C) {
    __shared__ __half tile[32][33];
    int e = blockIdx.z;
    in  += (size_t)e * R * C;
    out += (size_t)e * R * C;
    int c0 = blockIdx.x * 32, r0 = blockIdx.y * 32;
    int tx = threadIdx.x, ty = threadIdx.y;   // 32 x 8
#pragma unroll
    for (int i = 0; i < 32; i += 8)
        tile[ty + i][tx] = __float2half_rn(in[(size_t)(r0 + ty + i) * C + c0 + tx]);
    __syncthreads();
#pragma unroll
    for (int i = 0; i < 32; i += 8)
        out[(size_t)(c0 + ty + i) * R + r0 + tx] = tile[tx][ty + i];
}

// ---------------- gating (proven, fp32 exact) ----------------
__global__ void __launch_bounds__(256) gate_kernel(const float* __restrict__ x,
                                                   const float* __restrict__ wg) {
    __shared__ float swg[E_EXP][D_DIM];
    int tid = threadIdx.x;
    for (int i = tid; i < D_DIM * E_EXP; i += 256) {
        int d = i >> 3, e = i & 7;
        swg[e][d] = wg[i];
    }
    __syncthreads();

    int warp = tid >> 5, lane = tid & 31;
    int t = blockIdx.x * 8 + warp;
    const float* xr = x + (size_t)t * D_DIM;

    float acc[E_EXP];
#pragma unroll
    for (int e = 0; e < E_EXP; e++) acc[e] = 0.f;
    for (int d = lane; d < D_DIM; d += 32) {
        float xv = xr[d];
#pragma unroll
        for (int e = 0; e < E_EXP; e++) acc[e] = fmaf(xv, swg[e][d], acc[e]);
    }
#pragma unroll
    for (int e = 0; e < E_EXP; e++)
#pragma unroll
        for (int o = 16; o > 0; o >>= 1)
            acc[e] += __shfl_xor_sync(0xffffffffu, acc[e], o);

    if (lane == 0) {
        int e0 = 0; float l0 = acc[0];
#pragma unroll
        for (int e = 1; e < E_EXP; e++) if (acc[e] > l0) { l0 = acc[e]; e0 = e; }
        int e1 = -1; float l1 = -3.0e38f;
#pragma unroll
        for (int e = 0; e < E_EXP; e++) {
            if (e == e0) continue;
            if (acc[e] > l1) { l1 = acc[e]; e1 = e; }
        }
        float ex  = __expf(l1 - l0);
        float inv = 1.f / (1.f + ex);
        g_probs[2 * t]     = inv;
        g_probs[2 * t + 1] = ex * inv;
        int p0 = atomicAdd(&g_cnt[e0], 1);
        g_list[e0 * T_TOK + p0] = 2 * t;
        int p1 = atomicAdd(&g_cnt[e1], 1);
        g_list[e1 * T_TOK + p1] = 2 * t + 1;
    }
}

// =============================================================================
// fp16 GEMM core: 128x128 CTA tile, 256 threads, 8 warps (2m x 4n), warp 64x32.
// m16n8k16 MMA, 3-stage cp.async + mbarrier pipeline (R11-proven).
// EPI: 0 = raw fp32 -> g_Y, 1 = silu fp32 -> g_Hs, 2 = fp16(g_Hs * c) -> g_Hh.
// =============================================================================
template <int EPI>
__device__ __forceinline__ void gemm_core(const __half* __restrict__ Ag, int a_pair, int a_ld,
                                          const __half* __restrict__ Wt, int w_ld, int NCH,
                                          int dcol0, int n_e, int m0, char* smem) {
    int* slots = (int*)smem;
    uint32_t sb = smem_u32(smem);
    int tid = threadIdx.x, wid = tid >> 5, lane = tid & 31;

    if (tid == 0) {
#pragma unroll
        for (int s = 0; s < 3; s++) { MBAR_INIT(MBF(sb, s), 256); MBAR_INIT(MBE(sb, s), 256); }
    }
    __syncthreads();

    auto issue = [&](int ci, int s) {
        int k0 = ci * 32;                                  // halves
        uint32_t base = sb + 1024 + s * STG;
#pragma unroll
        for (int it = 0; it < 2; it++) {                   // A: 128 rows x 4 quads(16B)
            int idx = it * 256 + tid;
            int row = idx >> 2, kq = idx & 3;
            int r = a_pair ? (slots[row] >> 1) : slots[row];
            CP16(base + row * 80 + kq * 16, Ag + (size_t)r * a_ld + k0 + kq * 8);
        }
        uint32_t bb = base + TILE_BYTES;
#pragma unroll
        for (int it = 0; it < 2; it++) {                   // B: 128 n-rows x 4 quads
            int idx = it * 256 + tid;
            int row = idx >> 2, kq = idx & 3;
            CP16(bb + row * 80 + kq * 16, Wt + (size_t)row * w_ld + k0 + kq * 8);
        }
    };

    issue(0, 0); CPMBAR_ARRIVE(MBF(sb, 0));
    issue(1, 1); CPMBAR_ARRIVE(MBF(sb, 1));

    int g = lane >> 2, t = lane & 3;
    int m0w = (wid & 1) * 64, n0w = (wid >> 1) * 32;

    float c[4][4][4];
#pragma unroll
    for (int a = 0; a < 4; a++)
#pragma unroll
        for (int b = 0; b < 4; b++)
#pragma unroll
            for (int r = 0; r < 4; r++) c[a][b][r] = 0.f;

    int cs = 0, ck = 0;
    int ps = 2, pk = 0;
    for (int ci = 0; ci < NCH; ci++) {
        if (ci + 2 < NCH) {
            if (pk) mbar_wait(MBE(sb, ps), (pk - 1) & 1);
            issue(ci + 2, ps);
            CPMBAR_ARRIVE(MBF(sb, ps));
            if (++ps == 3) { ps = 0; ++pk; }
        }
        mbar_wait(MBF(sb, cs), ck);

        const __half* As = (const __half*)(smem + 1024 + cs * STG);
        const __half* Bs = As + TILE_BYTES / 2;

#pragma unroll
        for (int kk = 0; kk < 2; kk++) {                   // two k16 steps per 32-chunk
            uint32_t af[4][4], bf[4][2];
#pragma unroll
            for (int mf = 0; mf < 4; mf++) {
                const __half* ap = As + (m0w + mf * 16 + g) * ROW_H + kk * 16 + 2 * t;
                af[mf][0] = *(const uint32_t*)(ap);
                af[mf][1] = *(const uint32_t*)(ap + 8 * ROW_H);
                af[mf][2] = *(const uint32_t*)(ap + 8);
                af[mf][3] = *(const uint32_t*)(ap + 8 * ROW_H + 8);
            }
#pragma unroll
            for (int nf = 0; nf < 4; nf++) {
                const __half* bp = Bs + (n0w + nf * 8 + g) * ROW_H + kk * 16 + 2 * t;
                bf[nf][0] = *(const uint32_t*)(bp);
                bf[nf][1] = *(const uint32_t*)(bp + 8);
            }
#pragma unroll
            for (int mf = 0; mf < 4; mf++)
#pragma unroll
                for (int nf = 0; nf < 4; nf++)
                    MMA_F16(c[mf][nf], af[mf], bf[nf]);
        }
        MBAR_ARRIVE(MBE(sb, cs));
        if (++cs == 3) { cs = 0; ck ^= 1; }
    }

    // ---- epilogue ----
#pragma unroll
    for (int mf = 0; mf < 4; mf++) {
#pragma unroll
        for (int hh = 0; hh < 2; hh++) {
            int row = m0w + mf * 16 + g + 8 * hh;
            if (m0 + row >= n_e) continue;
            int slot = slots[row];
#pragma unroll
            for (int nf = 0; nf < 4; nf++) {
                int col = dcol0 + n0w + nf * 8 + 2 * t;
                float v0 = c[mf][nf][2 * hh + 0];
                float v1 = c[mf][nf][2 * hh + 1];
                if (EPI == 0) {
                    float2 o; o.x = v0; o.y = v1;
                    *(float2*)(g_Y + (size_t)slot * D_DIM + col) = o;
                } else if (EPI == 1) {
                    float2 o;
                    o.x = v0 / (1.f + __expf(-v0));
                    o.y = v1 / (1.f + __expf(-v1));
                    *(float2*)(g_Hs + (size_t)slot * F_DIM + col) = o;
                } else {
                    float2 s = *(const float2*)(g_Hs + (size_t)slot * F_DIM + col);
                    *(__half2*)(g_Hh + (size_t)slot * F_DIM + col) =
                        __floats2half2_rn(s.x * v0, s.y * v1);
                }
            }
        }
    }
}

// ============= GEMM1a: g_Hs = silu(gather(xh) @ w1) ===========================
__global__ void __launch_bounds__(256, 2) gemm1a_kernel() {
    int e   = blockIdx.z;
    int n_e = g_cnt[e];
    int m0  = blockIdx.x * 128;
    if (m0 >= n_e) return;
    int f0  = blockIdx.y * 128;

    extern __shared__ char smem[];
    int* slots = (int*)smem;
    int tid = threadIdx.x;
    if (tid < 128) {
        int m = m0 + tid;
        slots[tid] = g_list[e * T_TOK + (m < n_e ? m : m0)];
    }
    gemm_core<1>(g_xh, 1, D_DIM,
                 g_w1t + ((size_t)e * F_DIM + f0) * D_DIM, D_DIM,
                 D_DIM / 32, f0, n_e, m0, smem);
}

// ============= GEMM1b: g_Hh = fp16(g_Hs * (gather(xh) @ w3)) ==================
__global__ void __launch_bounds__(256, 2) gemm1b_kernel() {
    int e   = blockIdx.z;
    int n_e = g_cnt[e];
    int m0  = blockIdx.x * 128;
    if (m0 >= n_e) return;
    int f0  = blockIdx.y * 128;

    extern __shared__ char smem[];
    int* slots = (int*)smem;
    int tid = threadIdx.x;
    if (tid < 128) {
        int m = m0 + tid;
        slots[tid] = g_list[e * T_TOK + (m < n_e ? m : m0)];
    }
    gemm_core<2>(g_xh, 1, D_DIM,
                 g_w3t + ((size_t)e * F_DIM + f0) * D_DIM, D_DIM,
                 D_DIM / 32, f0, n_e, m0, smem);
}

// ============= GEMM2: g_Y = gather(g_Hh) @ w2 =================================
__global__ void __launch_bounds__(256, 2) gemm2_kernel() {
    int e   = blockIdx.z;
    int n_e = g_cnt[e];
    int m0  = blockIdx.x * 128;
    if (m0 >= n_e) return;
    int n0  = blockIdx.y * 128;

    extern __shared__ char smem[];
    int* slots = (int*)smem;
    int tid = threadIdx.x;
    if (tid < 128) {
        int m = m0 + tid;
        slots[tid] = g_list[e * T_TOK + (m < n_e ? m : m0)];
    }
    gemm_core<0>(g_Hh, 0, F_DIM,
                 g_w2t + ((size_t)e * D_DIM + n0) * F_DIM, F_DIM,
                 F_DIM / 32, n0, n_e, m0, smem);
}

// ---------------- combine ----------------
__global__ void __launch_bounds__(256) combine_kernel(float* __restrict__ out) {
    int idx = blockIdx.x * 256 + threadIdx.x;
    int t   = idx / (D_DIM / 4);
    int d4  = idx % (D_DIM / 4);
    float p0 = g_probs[2 * t], p1 = g_probs[2 * t + 1];
    const float4* y0 = (const float4*)(g_Y + (size_t)(2 * t) * D_DIM) + d4;
    const float4* y1 = (const float4*)(g_Y + (size_t)(2 * t + 1) * D_DIM) + d4;
    float4 a = *y0, b = *y1, o;
    o.x = p0 * a.x + p1 * b.x;
    o.y = p0 * a.y + p1 * b.y;
    o.z = p0 * a.z + p1 * b.z;
    o.w = p0 * a.w + p1 * b.w;
    *((float4*)(out + (size_t)t * D_DIM) + d4) = o;
}

// ---------------- launch ----------------
extern "C" void kernel_launch(void* const* d_in, const int* in_sizes, int n_in,
                              void* d_out, int out_size) {
    const float* x  = (const float*)d_in[0];
    const float* wg = (const float*)d_in[1];
    const float* w1 = (const float*)d_in[2];
    const float* w3 = (const float*)d_in[3];
    const float* w2 = (const float*)d_in[4];
    float* out = (float*)d_out;

    const int SMEM_G = 1024 + 3 * STG;   // 62464
    cudaFuncSetAttribute(gemm1a_kernel, cudaFuncAttributeMaxDynamicSharedMemorySize, SMEM_G);
    cudaFuncSetAttribute(gemm1b_kernel, cudaFuncAttributeMaxDynamicSharedMemorySize, SMEM_G);
    cudaFuncSetAttribute(gemm2_kernel,  cudaFuncAttributeMaxDynamicSharedMemorySize, SMEM_G);

    __half *xh, *w1t, *w3t, *w2t;
    cudaGetSymbolAddress((void**)&xh,  g_xh);
    cudaGetSymbolAddress((void**)&w1t, g_w1t);
    cudaGetSymbolAddress((void**)&w3t, g_w3t);
    cudaGetSymbolAddress((void**)&w2t, g_w2t);

    init_kernel<<<1, 32>>>();
    convert_x_kernel<<<2048, 256>>>((const float4*)x, (__half2*)xh);
    // w1/w3: [e][D][F] fp32 -> [e][F][D] fp16
    tconv_kernel<<<dim3(F_DIM / 32, D_DIM / 32, E_EXP), dim3(32, 8)>>>(w1, w1t, D_DIM, F_DIM);
    tconv_kernel<<<dim3(F_DIM / 32, D_DIM / 32, E_EXP), dim3(32, 8)>>>(w3, w3t, D_DIM, F_DIM);
    // w2: [e][F][D] fp32 -> [e][D][F] fp16
    tconv_kernel<<<dim3(D_DIM / 32, F_DIM / 32, E_EXP), dim3(32, 8)>>>(w2, w2t, F_DIM, D_DIM);
    gate_kernel<<<T_TOK / 8, 256>>>(x, wg);

    gemm1a_kernel<<<dim3(T_TOK / 128, F_DIM / 128, E_EXP), 256, SMEM_G>>>();
    gemm1b_kernel<<<dim3(T_TOK / 128, F_DIM / 128, E_EXP), 256, SMEM_G>>>();
    gemm2_kernel<<<dim3(T_TOK / 128, D_DIM / 128, E_EXP), 256, SMEM_G>>>();
    combine_kernel<<<(T_TOK * D_DIM / 4) / 256, 256>>>(out);
}

// round 15
// speedup vs baseline: 1.6405x; 1.0294x over previous
#include <cuda_runtime.h>
#include <cuda_fp16.h>
#include <cstdint>

#define T_TOK 8192
#define D_DIM 1024
#define E_EXP 8
#define F_DIM 2048
#define NSLOT (2 * T_TOK)

// ---------------- device-global scratch ----------------
__device__ int    g_cnt[E_EXP];
__device__ int    g_list[E_EXP * T_TOK];
__device__ float  g_probs[NSLOT];
__device__ __half g_xh[(size_t)T_TOK * D_DIM];          // fp16 x
__device__ __half g_w1t[(size_t)E_EXP * D_DIM * F_DIM]; // fp16, transposed [e][f][d]
__device__ __half g_w3t[(size_t)E_EXP * D_DIM * F_DIM]; // fp16, transposed [e][f][d]
__device__ __half g_w2t[(size_t)E_EXP * F_DIM * D_DIM]; // fp16, transposed [e][d][f]
__device__ float  g_Hs[(size_t)NSLOT * F_DIM];          // silu(x@w1), exact fp32
__device__ __half g_Hh[(size_t)NSLOT * F_DIM];          // fp16 H = fp16(silu * c3)
__device__ float  g_Y[(size_t)NSLOT * D_DIM];

// ---------------- helpers ----------------
__device__ __forceinline__ uint32_t smem_u32(const void* p) {
    uint32_t a;
    asm("{ .reg .u64 t; cvta.to.shared.u64 t, %1; cvt.u32.u64 %0, t; }" : "=r"(a) : "l"(p));
    return a;
}
#define CP16(dst, src) asm volatile("cp.async.cg.shared.global [%0], [%1], 16;" :: "r"(dst), "l"(src))

// mbarrier pipeline primitives (.noinc is load-bearing — R10 lesson)
#define MBAR_INIT(mb, c)  asm volatile("mbarrier.init.shared.b64 [%0], %1;" :: "r"(mb), "r"((uint32_t)(c)) : "memory")
#define MBAR_ARRIVE(mb)   asm volatile("mbarrier.arrive.shared.b64 _, [%0];" :: "r"(mb) : "memory")
#define CPMBAR_ARRIVE(mb) asm volatile("cp.async.mbarrier.arrive.noinc.shared.b64 [%0];" :: "r"(mb) : "memory")
__device__ __forceinline__ void mbar_wait(uint32_t mb, uint32_t parity) {
    uint32_t done;
    do {
        asm volatile("{ .reg .pred p; mbarrier.try_wait.parity.shared.b64 p, [%1], %2; selp.b32 %0, 1, 0, p; }"
                     : "=r"(done) : "r"(mb), "r"(parity) : "memory");
    } while (!done);
}

#define MMA_F16(c, a, b)                                                           \
    asm volatile("mma.sync.aligned.m16n8k16.row.col.f32.f16.f16.f32 "              \
                 "{%0,%1,%2,%3}, {%4,%5,%6,%7}, {%8,%9}, {%0,%1,%2,%3};"           \
                 : "+f"((c)[0]), "+f"((c)[1]), "+f"((c)[2]), "+f"((c)[3])          \
                 : "r"((a)[0]), "r"((a)[1]), "r"((a)[2]), "r"((a)[3]),             \
                   "r"((b)[0]), "r"((b)[1]))

#define LDSM_X4(r0, r1, r2, r3, addr)                                              \
    asm volatile("ldmatrix.sync.aligned.m8n8.x4.shared.b16 {%0,%1,%2,%3}, [%4];"   \
                 : "=r"(r0), "=r"(r1), "=r"(r2), "=r"(r3) : "r"(addr))
#define LDSM_X2(r0, r1, addr)                                                      \
    asm volatile("ldmatrix.sync.aligned.m8n8.x2.shared.b16 {%0,%1}, [%2];"         \
                 : "=r"(r0), "=r"(r1) : "r"(addr))

// smem: tiles of 128 rows x 32 halves, rows padded to 40 halves (80 B).
// bank check: addr4 = 20*row + t; 20*row mod 32 = {0,20,8,28,16,4,24,12} — conflict-free.
#define ROW_H 40
#define TILE_BYTES (128 * ROW_H * 2)   // 10240
#define STG (2 * TILE_BYTES)           // 20480 (A + B)
// smem map: [0..512) slots, [512..560) mbarriers, tiles @1024
#define MBF(sb, s) ((sb) + 512 + (s) * 8)
#define MBE(sb, s) ((sb) + 536 + (s) * 8)

// ---------------- init ----------------
__global__ void init_kernel() {
    if (threadIdx.x < E_EXP) g_cnt[threadIdx.x] = 0;
}

// ---------------- convert x: fp32 -> fp16 ----------------
__global__ void __launch_bounds__(256) convert_x_kernel(const float4* __restrict__ x,
                                                        __half2* __restrict__ xh) {
    const int n4 = T_TOK * D_DIM / 4;
    int i = blockIdx.x * 256 + threadIdx.x;
    int stride = gridDim.x * 256;
    for (; i < n4; i += stride) {
        float4 v = x[i];
        xh[2 * i + 0] = __floats2half2_rn(v.x, v.y);
        xh[2 * i + 1] = __floats2half2_rn(v.z, v.w);
    }
}

// ------- transpose + convert: in fp32 [e][R][C] -> out fp16 [e][C][R] --------
__global__ void tconv_kernel(const float* __restrict__ in, __half* __restrict__ out,
                             int R, int C) {
    __shared__ __half tile[32][33];
    int e = blockIdx.z;
    in  += (size_t)e * R * C;
    out += (size_t)e * R * C;
    int c0 = blockIdx.x * 32, r0 = blockIdx.y * 32;
    int tx = threadIdx.x, ty = threadIdx.y;   // 32 x 8
#pragma unroll
    for (int i = 0; i < 32; i += 8)
        tile[ty + i][tx] = __float2half_rn(in[(size_t)(r0 + ty + i) * C + c0 + tx]);
    __syncthreads();
#pragma unroll
    for (int i = 0; i < 32; i += 8)
        out[(size_t)(c0 + ty + i) * R + r0 + tx] = tile[tx][ty + i];
}

// ---------------- gating (proven, fp32 exact) ----------------
__global__ void __launch_bounds__(256) gate_kernel(const float* __restrict__ x,
                                                   const float* __restrict__ wg) {
    __shared__ float swg[E_EXP][D_DIM];
    int tid = threadIdx.x;
    for (int i = tid; i < D_DIM * E_EXP; i += 256) {
        int d = i >> 3, e = i & 7;
        swg[e][d] = wg[i];
    }
    __syncthreads();

    int warp = tid >> 5, lane = tid & 31;
    int t = blockIdx.x * 8 + warp;
    const float* xr = x + (size_t)t * D_DIM;

    float acc[E_EXP];
#pragma unroll
    for (int e = 0; e < E_EXP; e++) acc[e] = 0.f;
    for (int d = lane; d < D_DIM; d += 32) {
        float xv = xr[d];
#pragma unroll
        for (int e = 0; e < E_EXP; e++) acc[e] = fmaf(xv, swg[e][d], acc[e]);
    }
#pragma unroll
    for (int e = 0; e < E_EXP; e++)
#pragma unroll
        for (int o = 16; o > 0; o >>= 1)
            acc[e] += __shfl_xor_sync(0xffffffffu, acc[e], o);

    if (lane == 0) {
        int e0 = 0; float l0 = acc[0];
#pragma unroll
        for (int e = 1; e < E_EXP; e++) if (acc[e] > l0) { l0 = acc[e]; e0 = e; }
        int e1 = -1; float l1 = -3.0e38f;
#pragma unroll
        for (int e = 0; e < E_EXP; e++) {
            if (e == e0) continue;
            if (acc[e] > l1) { l1 = acc[e]; e1 = e; }
        }
        float ex  = __expf(l1 - l0);
        float inv = 1.f / (1.f + ex);
        g_probs[2 * t]     = inv;
        g_probs[2 * t + 1] = ex * inv;
        int p0 = atomicAdd(&g_cnt[e0], 1);
        g_list[e0 * T_TOK + p0] = 2 * t;
        int p1 = atomicAdd(&g_cnt[e1], 1);
        g_list[e1 * T_TOK + p1] = 2 * t + 1;
    }
}

// =============================================================================
// fp16 GEMM core: 128x128 CTA tile, 256 threads, 8 warps (2m x 4n), warp 64x32.
// m16n8k16 MMA with ldmatrix fragment loads, 3-stage cp.async + mbarrier.
// EPI: 0 = raw fp32 -> g_Y, 1 = silu fp32 -> g_Hs, 2 = fp16(g_Hs * c) -> g_Hh.
// =============================================================================
template <int EPI>
__device__ __forceinline__ void gemm_core(const __half* __restrict__ Ag, int a_pair, int a_ld,
                                          const __half* __restrict__ Wt, int w_ld, int NCH,
                                          int dcol0, int n_e, int m0, char* smem) {
    int* slots = (int*)smem;
    uint32_t sb = smem_u32(smem);
    int tid = threadIdx.x, wid = tid >> 5, lane = tid & 31;

    if (tid == 0) {
#pragma unroll
        for (int s = 0; s < 3; s++) { MBAR_INIT(MBF(sb, s), 256); MBAR_INIT(MBE(sb, s), 256); }
    }
    __syncthreads();

    auto issue = [&](int ci, int s) {
        int k0 = ci * 32;                                  // halves
        uint32_t base = sb + 1024 + s * STG;
#pragma unroll
        for (int it = 0; it < 2; it++) {                   // A: 128 rows x 4 quads(16B)
            int idx = it * 256 + tid;
            int row = idx >> 2, kq = idx & 3;
            int r = a_pair ? (slots[row] >> 1) : slots[row];
            CP16(base + row * 80 + kq * 16, Ag + (size_t)r * a_ld + k0 + kq * 8);
        }
        uint32_t bb = base + TILE_BYTES;
#pragma unroll
        for (int it = 0; it < 2; it++) {                   // B: 128 n-rows x 4 quads
            int idx = it * 256 + tid;
            int row = idx >> 2, kq = idx & 3;
            CP16(bb + row * 80 + kq * 16, Wt + (size_t)row * w_ld + k0 + kq * 8);
        }
    };

    issue(0, 0); CPMBAR_ARRIVE(MBF(sb, 0));
    issue(1, 1); CPMBAR_ARRIVE(MBF(sb, 1));

    int g = lane >> 2, t = lane & 3;
    int m0w = (wid & 1) * 64, n0w = (wid >> 1) * 32;

    // per-lane ldmatrix address components
    uint32_t laneA = (uint32_t)(lane & 15) * 80 + (uint32_t)(lane >> 4) * 16;
    uint32_t laneB = (uint32_t)(lane & 7) * 80 + (uint32_t)((lane >> 3) & 1) * 16;

    float c[4][4][4];
#pragma unroll
    for (int a = 0; a < 4; a++)
#pragma unroll
        for (int b = 0; b < 4; b++)
#pragma unroll
            for (int r = 0; r < 4; r++) c[a][b][r] = 0.f;

    int cs = 0, ck = 0;
    int ps = 2, pk = 0;
    for (int ci = 0; ci < NCH; ci++) {
        if (ci + 2 < NCH) {
            if (pk) mbar_wait(MBE(sb, ps), (pk - 1) & 1);
            issue(ci + 2, ps);
            CPMBAR_ARRIVE(MBF(sb, ps));
            if (++ps == 3) { ps = 0; ++pk; }
        }
        mbar_wait(MBF(sb, cs), ck);

        uint32_t abase = sb + 1024 + cs * STG + laneA;
        uint32_t bbase = sb + 1024 + cs * STG + TILE_BYTES + laneB;

#pragma unroll
        for (int kk = 0; kk < 2; kk++) {                   // two k16 steps per 32-chunk
            uint32_t af[4][4], bf[4][2];
#pragma unroll
            for (int mf = 0; mf < 4; mf++)
                LDSM_X4(af[mf][0], af[mf][1], af[mf][2], af[mf][3],
                        abase + (m0w + mf * 16) * 80 + kk * 32);
#pragma unroll
            for (int nf = 0; nf < 4; nf++)
                LDSM_X2(bf[nf][0], bf[nf][1],
                        bbase + (n0w + nf * 8) * 80 + kk * 32);
#pragma unroll
            for (int mf = 0; mf < 4; mf++)
#pragma unroll
                for (int nf = 0; nf < 4; nf++)
                    MMA_F16(c[mf][nf], af[mf], bf[nf]);
        }
        MBAR_ARRIVE(MBE(sb, cs));
        if (++cs == 3) { cs = 0; ck ^= 1; }
    }

    // ---- epilogue ----
#pragma unroll
    for (int mf = 0; mf < 4; mf++) {
#pragma unroll
        for (int hh = 0; hh < 2; hh++) {
            int row = m0w + mf * 16 + g + 8 * hh;
            if (m0 + row >= n_e) continue;
            int slot = slots[row];
#pragma unroll
            for (int nf = 0; nf < 4; nf++) {
                int col = dcol0 + n0w + nf * 8 + 2 * t;
                float v0 = c[mf][nf][2 * hh + 0];
                float v1 = c[mf][nf][2 * hh + 1];
                if (EPI == 0) {
                    float2 o; o.x = v0; o.y = v1;
                    *(float2*)(g_Y + (size_t)slot * D_DIM + col) = o;
                } else if (EPI == 1) {
                    float2 o;
                    o.x = v0 / (1.f + __expf(-v0));
                    o.y = v1 / (1.f + __expf(-v1));
                    *(float2*)(g_Hs + (size_t)slot * F_DIM + col) = o;
                } else {
                    float2 s = *(const float2*)(g_Hs + (size_t)slot * F_DIM + col);
                    *(__half2*)(g_Hh + (size_t)slot * F_DIM + col) =
                        __floats2half2_rn(s.x * v0, s.y * v1);
                }
            }
        }
    }
}

// ============= GEMM1a: g_Hs = silu(gather(xh) @ w1) ===========================
__global__ void __launch_bounds__(256, 2) gemm1a_kernel() {
    int e   = blockIdx.z;
    int n_e = g_cnt[e];
    int m0  = blockIdx.x * 128;
    if (m0 >= n_e) return;
    int f0  = blockIdx.y * 128;

    extern __shared__ char smem[];
    int* slots = (int*)smem;
    int tid = threadIdx.x;
    if (tid < 128) {
        int m = m0 + tid;
        slots[tid] = g_list[e * T_TOK + (m < n_e ? m : m0)];
    }
    gemm_core<1>(g_xh, 1, D_DIM,
                 g_w1t + ((size_t)e * F_DIM + f0) * D_DIM, D_DIM,
                 D_DIM / 32, f0, n_e, m0, smem);
}

// ============= GEMM1b: g_Hh = fp16(g_Hs * (gather(xh) @ w3)) ==================
__global__ void __launch_bounds__(256, 2) gemm1b_kernel() {
    int e   = blockIdx.z;
    int n_e = g_cnt[e];
    int m0  = blockIdx.x * 128;
    if (m0 >= n_e) return;
    int f0  = blockIdx.y * 128;

    extern __shared__ char smem[];
    int* slots = (int*)smem;
    int tid = threadIdx.x;
    if (tid < 128) {
        int m = m0 + tid;
        slots[tid] = g_list[e * T_TOK + (m < n_e ? m : m0)];
    }
    gemm_core<2>(g_xh, 1, D_DIM,
                 g_w3t + ((size_t)e * F_DIM + f0) * D_DIM, D_DIM,
                 D_DIM / 32, f0, n_e, m0, smem);
}

// ============= GEMM2: g_Y = gather(g_Hh) @ w2 =================================
__global__ void __launch_bounds__(256, 2) gemm2_kernel() {
    int e   = blockIdx.z;
    int n_e = g_cnt[e];
    int m0  = blockIdx.x * 128;
    if (m0 >= n_e) return;
    int n0  = blockIdx.y * 128;

    extern __shared__ char smem[];
    int* slots = (int*)smem;
    int tid = threadIdx.x;
    if (tid < 128) {
        int m = m0 + tid;
        slots[tid] = g_list[e * T_TOK + (m < n_e ? m : m0)];
    }
    gemm_core<0>(g_Hh, 0, F_DIM,
                 g_w2t + ((size_t)e * D_DIM + n0) * F_DIM, F_DIM,
                 F_DIM / 32, n0, n_e, m0, smem);
}

// ---------------- combine ----------------
__global__ void __launch_bounds__(256) combine_kernel(float* __restrict__ out) {
    int idx = blockIdx.x * 256 + threadIdx.x;
    int t   = idx / (D_DIM / 4);
    int d4  = idx % (D_DIM / 4);
    float p0 = g_probs[2 * t], p1 = g_probs[2 * t + 1];
    const float4* y0 = (const float4*)(g_Y + (size_t)(2 * t) * D_DIM) + d4;
    const float4* y1 = (const float4*)(g_Y + (size_t)(2 * t + 1) * D_DIM) + d4;
    float4 a = *y0, b = *y1, o;
    o.x = p0 * a.x + p1 * b.x;
    o.y = p0 * a.y + p1 * b.y;
    o.z = p0 * a.z + p1 * b.z;
    o.w = p0 * a.w + p1 * b.w;
    *((float4*)(out + (size_t)t * D_DIM) + d4) = o;
}

// ---------------- launch ----------------
extern "C" void kernel_launch(void* const* d_in, const int* in_sizes, int n_in,
                              void* d_out, int out_size) {
    const float* x  = (const float*)d_in[0];
    const float* wg = (const float*)d_in[1];
    const float* w1 = (const float*)d_in[2];
    const float* w3 = (const float*)d_in[3];
    const float* w2 = (const float*)d_in[4];
    float* out = (float*)d_out;

    const int SMEM_G = 1024 + 3 * STG;   // 62464
    cudaFuncSetAttribute(gemm1a_kernel, cudaFuncAttributeMaxDynamicSharedMemorySize, SMEM_G);
    cudaFuncSetAttribute(gemm1b_kernel, cudaFuncAttributeMaxDynamicSharedMemorySize, SMEM_G);
    cudaFuncSetAttribute(gemm2_kernel,  cudaFuncAttributeMaxDynamicSharedMemorySize, SMEM_G);

    __half *xh, *w1t, *w3t, *w2t;
    cudaGetSymbolAddress((void**)&xh,  g_xh);
    cudaGetSymbolAddress((void**)&w1t, g_w1t);
    cudaGetSymbolAddress((void**)&w3t, g_w3t);
    cudaGetSymbolAddress((void**)&w2t, g_w2t);

    init_kernel<<<1, 32>>>();
    convert_x_kernel<<<2048, 256>>>((const float4*)x, (__half2*)xh);
    // w1/w3: [e][D][F] fp32 -> [e][F][D] fp16
    tconv_kernel<<<dim3(F_DIM / 32, D_DIM / 32, E_EXP), dim3(32, 8)>>>(w1, w1t, D_DIM, F_DIM);
    tconv_kernel<<<dim3(F_DIM / 32, D_DIM / 32, E_EXP), dim3(32, 8)>>>(w3, w3t, D_DIM, F_DIM);
    // w2: [e][F][D] fp32 -> [e][D][F] fp16
    tconv_kernel<<<dim3(D_DIM / 32, F_DIM / 32, E_EXP), dim3(32, 8)>>>(w2, w2t, F_DIM, D_DIM);
    gate_kernel<<<T_TOK / 8, 256>>>(x, wg);

    gemm1a_kernel<<<dim3(T_TOK / 128, F_DIM / 128, E_EXP), 256, SMEM_G>>>();
    gemm1b_kernel<<<dim3(T_TOK / 128, F_DIM / 128, E_EXP), 256, SMEM_G>>>();
    gemm2_kernel<<<dim3(T_TOK / 128, D_DIM / 128, E_EXP), 256, SMEM_G>>>();
    combine_kernel<<<(T_TOK * D_DIM / 4) / 256, 256>>>(out);
}

// round 16
// speedup vs baseline: 1.7912x; 1.0919x over previous
#include <cuda_runtime.h>
#include <cuda_fp16.h>
#include <cstdint>

#define T_TOK 8192
#define D_DIM 1024
#define E_EXP 8
#define F_DIM 2048
#define NSLOT (2 * T_TOK)

// ---------------- device-global scratch ----------------
__device__ int    g_cnt[E_EXP];
__device__ int    g_list[E_EXP * T_TOK];
__device__ float  g_probs[NSLOT];
__device__ __half g_xh[(size_t)T_TOK * D_DIM];          // fp16 x
__device__ __half g_w1t[(size_t)E_EXP * D_DIM * F_DIM]; // fp16, transposed [e][f][d]
__device__ __half g_w3t[(size_t)E_EXP * D_DIM * F_DIM]; // fp16, transposed [e][f][d]
__device__ __half g_w2t[(size_t)E_EXP * F_DIM * D_DIM]; // fp16, transposed [e][d][f]
__device__ float  g_Hs[(size_t)NSLOT * F_DIM];          // silu(x@w1), exact fp32
__device__ __half g_Hh[(size_t)NSLOT * F_DIM];          // fp16 H = fp16(silu * c3)
__device__ float  g_Y[(size_t)NSLOT * D_DIM];

// ---------------- helpers ----------------
__device__ __forceinline__ uint32_t smem_u32(const void* p) {
    uint32_t a;
    asm("{ .reg .u64 t; cvta.to.shared.u64 t, %1; cvt.u32.u64 %0, t; }" : "=r"(a) : "l"(p));
    return a;
}
#define CP16(dst, src) asm volatile("cp.async.cg.shared.global [%0], [%1], 16;" :: "r"(dst), "l"(src))

// mbarrier pipeline primitives (.noinc is load-bearing — R10 lesson)
#define MBAR_INIT(mb, c)  asm volatile("mbarrier.init.shared.b64 [%0], %1;" :: "r"(mb), "r"((uint32_t)(c)) : "memory")
#define MBAR_ARRIVE(mb)   asm volatile("mbarrier.arrive.shared.b64 _, [%0];" :: "r"(mb) : "memory")
#define CPMBAR_ARRIVE(mb) asm volatile("cp.async.mbarrier.arrive.noinc.shared.b64 [%0];" :: "r"(mb) : "memory")
__device__ __forceinline__ void mbar_wait(uint32_t mb, uint32_t parity) {
    uint32_t done;
    do {
        asm volatile("{ .reg .pred p; mbarrier.try_wait.parity.shared.b64 p, [%1], %2; selp.b32 %0, 1, 0, p; }"
                     : "=r"(done) : "r"(mb), "r"(parity) : "memory");
    } while (!done);
}

#define MMA_F16(c, a, b)                                                           \
    asm volatile("mma.sync.aligned.m16n8k16.row.col.f32.f16.f16.f32 "              \
                 "{%0,%1,%2,%3}, {%4,%5,%6,%7}, {%8,%9}, {%0,%1,%2,%3};"           \
                 : "+f"((c)[0]), "+f"((c)[1]), "+f"((c)[2]), "+f"((c)[3])          \
                 : "r"((a)[0]), "r"((a)[1]), "r"((a)[2]), "r"((a)[3]),             \
                   "r"((b)[0]), "r"((b)[1]))

#define LDSM_X4(r0, r1, r2, r3, addr)                                              \
    asm volatile("ldmatrix.sync.aligned.m8n8.x4.shared.b16 {%0,%1,%2,%3}, [%4];"   \
                 : "=r"(r0), "=r"(r1), "=r"(r2), "=r"(r3) : "r"(addr))

// smem: tiles of 128 rows x 64 halves, rows padded to 72 halves (144 B).
// ldmatrix bank check: 36*row mod 32 over any 8 consecutive rows = {0,4,...,28}
// in 4B units — each row's 16B quad hits distinct banks — conflict-free.
#define ROW_H 72
#define ROW_B 144
#define TILE_BYTES (128 * ROW_B)       // 18432
#define STG (2 * TILE_BYTES)           // 36864 (A + B)
// smem map: [0..512) slots, [512..560) mbarriers, tiles @1024
#define MBF(sb, s) ((sb) + 512 + (s) * 8)
#define MBE(sb, s) ((sb) + 536 + (s) * 8)

// ---------------- init ----------------
__global__ void init_kernel() {
    if (threadIdx.x < E_EXP) g_cnt[threadIdx.x] = 0;
}

// ---------------- convert x: fp32 -> fp16 ----------------
__global__ void __launch_bounds__(256) convert_x_kernel(const float4* __restrict__ x,
                                                        __half2* __restrict__ xh) {
    const int n4 = T_TOK * D_DIM / 4;
    int i = blockIdx.x * 256 + threadIdx.x;
    int stride = gridDim.x * 256;
    for (; i < n4; i += stride) {
        float4 v = x[i];
        xh[2 * i + 0] = __floats2half2_rn(v.x, v.y);
        xh[2 * i + 1] = __floats2half2_rn(v.z, v.w);
    }
}

// ------- transpose + convert: in fp32 [e][R][C] -> out fp16 [e][C][R] --------
__global__ void tconv_kernel(const float* __restrict__ in, __half* __restrict__ out,
                             int R, int C) {
    __shared__ __half tile[32][33];
    int e = blockIdx.z;
    in  += (size_t)e * R * C;
    out += (size_t)e * R * C;
    int c0 = blockIdx.x * 32, r0 = blockIdx.y * 32;
    int tx = threadIdx.x, ty = threadIdx.y;   // 32 x 8
#pragma unroll
    for (int i = 0; i < 32; i += 8)
        tile[ty + i][tx] = __float2half_rn(in[(size_t)(r0 + ty + i) * C + c0 + tx]);
    __syncthreads();
#pragma unroll
    for (int i = 0; i < 32; i += 8)
        out[(size_t)(c0 + ty + i) * R + r0 + tx] = tile[tx][ty + i];
}

// ---------------- gating (proven, fp32 exact) ----------------
__global__ void __launch_bounds__(256) gate_kernel(const float* __restrict__ x,
                                                   const float* __restrict__ wg) {
    __shared__ float swg[E_EXP][D_DIM];
    int tid = threadIdx.x;
    for (int i = tid; i < D_DIM * E_EXP; i += 256) {
        int d = i >> 3, e = i & 7;
        swg[e][d] = wg[i];
    }
    __syncthreads();

    int warp = tid >> 5, lane = tid & 31;
    int t = blockIdx.x * 8 + warp;
    const float* xr = x + (size_t)t * D_DIM;

    float acc[E_EXP];
#pragma unroll
    for (int e = 0; e < E_EXP; e++) acc[e] = 0.f;
    for (int d = lane; d < D_DIM; d += 32) {
        float xv = xr[d];
#pragma unroll
        for (int e = 0; e < E_EXP; e++) acc[e] = fmaf(xv, swg[e][d], acc[e]);
    }
#pragma unroll
    for (int e = 0; e < E_EXP; e++)
#pragma unroll
        for (int o = 16; o > 0; o >>= 1)
            acc[e] += __shfl_xor_sync(0xffffffffu, acc[e], o);

    if (lane == 0) {
        int e0 = 0; float l0 = acc[0];
#pragma unroll
        for (int e = 1; e < E_EXP; e++) if (acc[e] > l0) { l0 = acc[e]; e0 = e; }
        int e1 = -1; float l1 = -3.0e38f;
#pragma unroll
        for (int e = 0; e < E_EXP; e++) {
            if (e == e0) continue;
            if (acc[e] > l1) { l1 = acc[e]; e1 = e; }
        }
        float ex  = __expf(l1 - l0);
        float inv = 1.f / (1.f + ex);
        g_probs[2 * t]     = inv;
        g_probs[2 * t + 1] = ex * inv;
        int p0 = atomicAdd(&g_cnt[e0], 1);
        g_list[e0 * T_TOK + p0] = 2 * t;
        int p1 = atomicAdd(&g_cnt[e1], 1);
        g_list[e1 * T_TOK + p1] = 2 * t + 1;
    }
}

// =============================================================================
// fp16 GEMM core: 128x128 CTA tile, 256 threads, 8 warps (2m x 4n), warp 64x32.
// K-chunk 64 (4 k16 steps), 3-stage cp.async + mbarrier, ldmatrix fragments.
// EPI: 0 = raw fp32 -> g_Y, 1 = silu fp32 -> g_Hs, 2 = fp16(g_Hs * c) -> g_Hh.
// =============================================================================
template <int EPI>
__device__ __forceinline__ void gemm_core(const __half* __restrict__ Ag, int a_pair, int a_ld,
                                          const __half* __restrict__ Wt, int w_ld, int NCH,
                                          int dcol0, int n_e, int m0, char* smem) {
    int* slots = (int*)smem;
    uint32_t sb = smem_u32(smem);
    int tid = threadIdx.x, wid = tid >> 5, lane = tid & 31;

    if (tid == 0) {
#pragma unroll
        for (int s = 0; s < 3; s++) { MBAR_INIT(MBF(sb, s), 256); MBAR_INIT(MBE(sb, s), 256); }
    }
    __syncthreads();

    auto issue = [&](int ci, int s) {
        int k0 = ci * 64;                                  // halves
        uint32_t base = sb + 1024 + s * STG;
#pragma unroll
        for (int it = 0; it < 4; it++) {                   // A: 128 rows x 8 quads(16B)
            int idx = it * 256 + tid;
            int row = idx >> 3, kq = idx & 7;
            int r = a_pair ? (slots[row] >> 1) : slots[row];
            CP16(base + row * ROW_B + kq * 16, Ag + (size_t)r * a_ld + k0 + kq * 8);
        }
        uint32_t bb = base + TILE_BYTES;
#pragma unroll
        for (int it = 0; it < 4; it++) {                   // B: 128 n-rows x 8 quads
            int idx = it * 256 + tid;
            int row = idx >> 3, kq = idx & 7;
            CP16(bb + row * ROW_B + kq * 16, Wt + (size_t)row * w_ld + k0 + kq * 8);
        }
    };

    issue(0, 0); CPMBAR_ARRIVE(MBF(sb, 0));
    issue(1, 1); CPMBAR_ARRIVE(MBF(sb, 1));

    int g = lane >> 2, t = lane & 3;
    int m0w = (wid & 1) * 64, n0w = (wid >> 1) * 32;

    // per-lane ldmatrix address components
    uint32_t laneA = (uint32_t)(lane & 15) * ROW_B + (uint32_t)(lane >> 4) * 16;
    // B x4: lanes 0-7 -> rows n..n+7 (k lo16B), 8-15 -> k hi16B, 16-31 -> rows n+8..n+15
    uint32_t laneB = (uint32_t)(lane & 7) * ROW_B + (uint32_t)((lane >> 3) & 1) * 16
                   + (uint32_t)(lane >> 4) * (8 * ROW_B);

    float c[4][4][4];
#pragma unroll
    for (int a = 0; a < 4; a++)
#pragma unroll
        for (int b = 0; b < 4; b++)
#pragma unroll
            for (int r = 0; r < 4; r++) c[a][b][r] = 0.f;

    int cs = 0, ck = 0;
    int ps = 2, pk = 0;
    for (int ci = 0; ci < NCH; ci++) {
        if (ci + 2 < NCH) {
            if (pk) mbar_wait(MBE(sb, ps), (pk - 1) & 1);
            issue(ci + 2, ps);
            CPMBAR_ARRIVE(MBF(sb, ps));
            if (++ps == 3) { ps = 0; ++pk; }
        }
        mbar_wait(MBF(sb, cs), ck);

        uint32_t abase = sb + 1024 + cs * STG + laneA;
        uint32_t bbase = sb + 1024 + cs * STG + TILE_BYTES + laneB;

#pragma unroll
        for (int kk = 0; kk < 4; kk++) {                   // four k16 steps per 64-chunk
            uint32_t af[4][4], bf[4][2];
#pragma unroll
            for (int mf = 0; mf < 4; mf++)
                LDSM_X4(af[mf][0], af[mf][1], af[mf][2], af[mf][3],
                        abase + (m0w + mf * 16) * ROW_B + kk * 32);
#pragma unroll
            for (int np = 0; np < 2; np++)                 // nf pairs {0,1},{2,3}
                LDSM_X4(bf[2 * np][0], bf[2 * np][1], bf[2 * np + 1][0], bf[2 * np + 1][1],
                        bbase + (n0w + np * 16) * ROW_B + kk * 32);
#pragma unroll
            for (int mf = 0; mf < 4; mf++)
#pragma unroll
                for (int nf = 0; nf < 4; nf++)
                    MMA_F16(c[mf][nf], af[mf], bf[nf]);
        }
        MBAR_ARRIVE(MBE(sb, cs));
        if (++cs == 3) { cs = 0; ck ^= 1; }
    }

    // ---- epilogue ----
#pragma unroll
    for (int mf = 0; mf < 4; mf++) {
#pragma unroll
        for (int hh = 0; hh < 2; hh++) {
            int row = m0w + mf * 16 + g + 8 * hh;
            if (m0 + row >= n_e) continue;
            int slot = slots[row];
#pragma unroll
            for (int nf = 0; nf < 4; nf++) {
                int col = dcol0 + n0w + nf * 8 + 2 * t;
                float v0 = c[mf][nf][2 * hh + 0];
                float v1 = c[mf][nf][2 * hh + 1];
                if (EPI == 0) {
                    float2 o; o.x = v0; o.y = v1;
                    *(float2*)(g_Y + (size_t)slot * D_DIM + col) = o;
                } else if (EPI == 1) {
                    float2 o;
                    o.x = v0 / (1.f + __expf(-v0));
                    o.y = v1 / (1.f + __expf(-v1));
                    *(float2*)(g_Hs + (size_t)slot * F_DIM + col) = o;
                } else {
                    float2 s = *(const float2*)(g_Hs + (size_t)slot * F_DIM + col);
                    *(__half2*)(g_Hh + (size_t)slot * F_DIM + col) =
                        __floats2half2_rn(s.x * v0, s.y * v1);
                }
            }
        }
    }
}

// ============= GEMM1a: g_Hs = silu(gather(xh) @ w1) ===========================
__global__ void __launch_bounds__(256, 2) gemm1a_kernel() {
    int e   = blockIdx.z;
    int n_e = g_cnt[e];
    int m0  = blockIdx.x * 128;
    if (m0 >= n_e) return;
    int f0  = blockIdx.y * 128;

    extern __shared__ char smem[];
    int* slots = (int*)smem;
    int tid = threadIdx.x;
    if (tid < 128) {
        int m = m0 + tid;
        slots[tid] = g_list[e * T_TOK + (m < n_e ? m : m0)];
    }
    gemm_core<1>(g_xh, 1, D_DIM,
                 g_w1t + ((size_t)e * F_DIM + f0) * D_DIM, D_DIM,
                 D_DIM / 64, f0, n_e, m0, smem);
}

// ============= GEMM1b: g_Hh = fp16(g_Hs * (gather(xh) @ w3)) ==================
__global__ void __launch_bounds__(256, 2) gemm1b_kernel() {
    int e   = blockIdx.z;
    int n_e = g_cnt[e];
    int m0  = blockIdx.x * 128;
    if (m0 >= n_e) return;
    int f0  = blockIdx.y * 128;

    extern __shared__ char smem[];
    int* slots = (int*)smem;
    int tid = threadIdx.x;
    if (tid < 128) {
        int m = m0 + tid;
        slots[tid] = g_list[e * T_TOK + (m < n_e ? m : m0)];
    }
    gemm_core<2>(g_xh, 1, D_DIM,
                 g_w3t + ((size_t)e * F_DIM + f0) * D_DIM, D_DIM,
                 D_DIM / 64, f0, n_e, m0, smem);
}

// ============= GEMM2: g_Y = gather(g_Hh) @ w2 =================================
__global__ void __launch_bounds__(256, 2) gemm2_kernel() {
    int e   = blockIdx.z;
    int n_e = g_cnt[e];
    int m0  = blockIdx.x * 128;
    if (m0 >= n_e) return;
    int n0  = blockIdx.y * 128;

    extern __shared__ char smem[];
    int* slots = (int*)smem;
    int tid = threadIdx.x;
    if (tid < 128) {
        int m = m0 + tid;
        slots[tid] = g_list[e * T_TOK + (m < n_e ? m : m0)];
    }
    gemm_core<0>(g_Hh, 0, F_DIM,
                 g_w2t + ((size_t)e * D_DIM + n0) * F_DIM, F_DIM,
                 F_DIM / 64, n0, n_e, m0, smem);
}

// ---------------- combine ----------------
__global__ void __launch_bounds__(256) combine_kernel(float* __restrict__ out) {
    int idx = blockIdx.x * 256 + threadIdx.x;
    int t   = idx / (D_DIM / 4);
    int d4  = idx % (D_DIM / 4);
    float p0 = g_probs[2 * t], p1 = g_probs[2 * t + 1];
    const float4* y0 = (const float4*)(g_Y + (size_t)(2 * t) * D_DIM) + d4;
    const float4* y1 = (const float4*)(g_Y + (size_t)(2 * t + 1) * D_DIM) + d4;
    float4 a = *y0, b = *y1, o;
    o.x = p0 * a.x + p1 * b.x;
    o.y = p0 * a.y + p1 * b.y;
    o.z = p0 * a.z + p1 * b.z;
    o.w = p0 * a.w + p1 * b.w;
    *((float4*)(out + (size_t)t * D_DIM) + d4) = o;
}

// ---------------- launch ----------------
extern "C" void kernel_launch(void* const* d_in, const int* in_sizes, int n_in,
                              void* d_out, int out_size) {
    const float* x  = (const float*)d_in[0];
    const float* wg = (const float*)d_in[1];
    const float* w1 = (const float*)d_in[2];
    const float* w3 = (const float*)d_in[3];
    const float* w2 = (const float*)d_in[4];
    float* out = (float*)d_out;

    const int SMEM_G = 1024 + 3 * STG;   // 111616
    cudaFuncSetAttribute(gemm1a_kernel, cudaFuncAttributeMaxDynamicSharedMemorySize, SMEM_G);
    cudaFuncSetAttribute(gemm1b_kernel, cudaFuncAttributeMaxDynamicSharedMemorySize, SMEM_G);
    cudaFuncSetAttribute(gemm2_kernel,  cudaFuncAttributeMaxDynamicSharedMemorySize, SMEM_G);

    __half *xh, *w1t, *w3t, *w2t;
    cudaGetSymbolAddress((void**)&xh,  g_xh);
    cudaGetSymbolAddress((void**)&w1t, g_w1t);
    cudaGetSymbolAddress((void**)&w3t, g_w3t);
    cudaGetSymbolAddress((void**)&w2t, g_w2t);

    init_kernel<<<1, 32>>>();
    convert_x_kernel<<<2048, 256>>>((const float4*)x, (__half2*)xh);
    // w1/w3: [e][D][F] fp32 -> [e][F][D] fp16
    tconv_kernel<<<dim3(F_DIM / 32, D_DIM / 32, E_EXP), dim3(32, 8)>>>(w1, w1t, D_DIM, F_DIM);
    tconv_kernel<<<dim3(F_DIM / 32, D_DIM / 32, E_EXP), dim3(32, 8)>>>(w3, w3t, D_DIM, F_DIM);
    // w2: [e][F][D] fp32 -> [e][D][F] fp16
    tconv_kernel<<<dim3(D_DIM / 32, F_DIM / 32, E_EXP), dim3(32, 8)>>>(w2, w2t, F_DIM, D_DIM);
    gate_kernel<<<T_TOK / 8, 256>>>(x, wg);

    gemm1a_kernel<<<dim3(T_TOK / 128, F_DIM / 128, E_EXP), 256, SMEM_G>>>();
    gemm1b_kernel<<<dim3(T_TOK / 128, F_DIM / 128, E_EXP), 256, SMEM_G>>>();
    gemm2_kernel<<<dim3(T_TOK / 128, D_DIM / 128, E_EXP), 256, SMEM_G>>>();
    combine_kernel<<<(T_TOK * D_DIM / 4) / 256, 256>>>(out);
}